// round 12
// baseline (speedup 1.0000x reference)
#include <cuda_runtime.h>
#include <cstdint>
#include <math.h>

// ===========================================================================
// MMFConv2d sm_103a (base-target-safe), Round 12:
//   R10 s8 pipeline with the I2F flood replaced by the magic-number trick:
//   IMMA C-operand = 0x4B400000 -> s32 result reinterprets as float
//   12582912 + G (|G|<=8192 exact); FADD recovers float(G) exactly; FFMA
//   folds per-input-pixel inv_s. Zero cvt instructions.
// ===========================================================================

#define MAGIC_I 0x4B400000
#define MAGIC_F 12582912.0f

__device__ unsigned char g_a8[(size_t)8 * 65536 * 64];   // s8 NHWC
__device__ float g_invs[8 * 65536];                      // per-pixel inv_s
__device__ char  g_w8[9 * 64 * 64];                      // [tap][co][ci]
__device__ float g_inv_sw;

// ---------------------------------------------------------------------------
__device__ __forceinline__ uint32_t smem_u32(const void* p) {
    uint32_t a;
    asm("{ .reg .u64 t; cvta.to.shared.u64 t, %1; cvt.u32.u64 %0, t; }"
        : "=r"(a) : "l"(p));
    return a;
}
__device__ __forceinline__ void ldsm_x4(uint32_t (&r)[4], uint32_t a) {
    asm volatile("ldmatrix.sync.aligned.m8n8.x4.shared.b16 {%0,%1,%2,%3}, [%4];"
                 : "=r"(r[0]), "=r"(r[1]), "=r"(r[2]), "=r"(r[3]) : "r"(a));
}
__device__ __forceinline__ void ldsm_x2(uint32_t (&r)[2], uint32_t a) {
    asm volatile("ldmatrix.sync.aligned.m8n8.x2.shared.b16 {%0,%1}, [%2];"
                 : "=r"(r[0]), "=r"(r[1]) : "r"(a));
}
// D = A*B + magic (per-element bias 0x4B400000)
__device__ __forceinline__ void imma_m(int (&d)[4], const uint32_t (&a)[4],
                                       const uint32_t (&b)[2]) {
    asm volatile(
        "mma.sync.aligned.m16n8k32.row.col.s32.s8.s8.s32 "
        "{%0,%1,%2,%3}, {%4,%5,%6,%7}, {%8,%9}, {%10,%10,%10,%10};"
        : "=r"(d[0]), "=r"(d[1]), "=r"(d[2]), "=r"(d[3])
        : "r"(a[0]), "r"(a[1]), "r"(a[2]), "r"(a[3]), "r"(b[0]), "r"(b[1]),
          "r"(MAGIC_I));
}
// D += A*B
__device__ __forceinline__ void imma(int (&d)[4], const uint32_t (&a)[4],
                                     const uint32_t (&b)[2]) {
    asm volatile(
        "mma.sync.aligned.m16n8k32.row.col.s32.s8.s8.s32 "
        "{%0,%1,%2,%3}, {%4,%5,%6,%7}, {%8,%9}, {%0,%1,%2,%3};"
        : "+r"(d[0]), "+r"(d[1]), "+r"(d[2]), "+r"(d[3])
        : "r"(a[0]), "r"(a[1]), "r"(a[2]), "r"(a[3]), "r"(b[0]), "r"(b[1]));
}
#define CP_ASYNC(dst, src, n) \
    asm volatile("cp.async.cg.shared.global [%0], [%1], 16, %2;" \
                 :: "r"(dst), "l"(src), "r"(n) : "memory")
#define CP_COMMIT() asm volatile("cp.async.commit_group;" ::: "memory")
#define CP_WAIT0()  asm volatile("cp.async.wait_group 0;" ::: "memory")
#define STS128Z(a) \
    asm volatile("st.shared.v4.b32 [%0], {%1,%1,%1,%1};" :: "r"(a), "r"(0) : "memory")

// ---------------------------------------------------------------------------
// smem layout (s8 act rows: 64B per pixel)
// ---------------------------------------------------------------------------
#define WS_OFF     0                         // 9 * 4096 = 36864
#define ACT_OFF    36864                     // 4 slots * 16512
#define SLOT_B     16512                     // 258 px * 64 B
#define INVS_OFF   (ACT_OFF + 4 * SLOT_B)    // 102912; 4 slots * 1056 B
#define INVS_SLOT  1056
#define BIAS_OFF   (INVS_OFF + 4 * INVS_SLOT)
#define SMEM_BYTES (BIAS_OFF + 256)          // ~107.5 KB

// ---------------------------------------------------------------------------
// Kernel 1 (proven): per-pixel LN + int8 quant -> s8 NHWC + inv_s
// ---------------------------------------------------------------------------
__global__ void __launch_bounds__(128) norm_quant_kernel(const float* __restrict__ x) {
    int p  = blockIdx.x * 128 + threadIdx.x;
    int b  = p >> 16;
    int sp = p & 65535;

    const float* xb = x + (size_t)b * 64 * 65536 + sp;

    float v[64];
    float sum = 0.f;
#pragma unroll
    for (int c = 0; c < 64; c++) { v[c] = xb[(size_t)c << 16]; sum += v[c]; }
    float mu = sum * (1.0f / 64.0f);

    float var = 0.f, mx = 0.f;
#pragma unroll
    for (int c = 0; c < 64; c++) {
        float d = v[c] - mu;
        var += d * d;
        mx = fmaxf(mx, fabsf(d));
    }
    var *= (1.0f / 64.0f);
    float r = rsqrtf(var + 1e-8f);

    float maxn  = fmaxf(mx * r, 1e-8f);
    float s     = 127.0f / maxn;
    float inv_s = maxn * (1.0f / 127.0f);

    unsigned char* yb = g_a8 + ((size_t)p << 6);
#pragma unroll
    for (int c4 = 0; c4 < 4; c4++) {
        uint4 wv;
        uint32_t wds[4];
#pragma unroll
        for (int jj = 0; jj < 4; jj++) {
            int ci = (c4 << 4) + (jj << 2);
            int q0 = (int)rintf(s * (r * (v[ci + 0] - mu)));
            int q1 = (int)rintf(s * (r * (v[ci + 1] - mu)));
            int q2 = (int)rintf(s * (r * (v[ci + 2] - mu)));
            int q3 = (int)rintf(s * (r * (v[ci + 3] - mu)));
            wds[jj] = (q0 & 255) | ((q1 & 255) << 8) | ((q2 & 255) << 16)
                    | ((q3 & 255) << 24);
        }
        wv.x = wds[0]; wv.y = wds[1]; wv.z = wds[2]; wv.w = wds[3];
        *(uint4*)(yb + (c4 << 4)) = wv;
    }
    g_invs[p] = inv_s;
}

// ---------------------------------------------------------------------------
// Kernel 2 (proven): ternary weight quant -> s8 [tap][co][ci]
// ---------------------------------------------------------------------------
__global__ void __launch_bounds__(512) wq_kernel(const float* __restrict__ Wt) {
    __shared__ float red[16];
    __shared__ float s_w_sh;
    int tid = threadIdx.x;

    float sum = 0.f;
    for (int i = tid; i < 36864; i += 512) sum += fabsf(Wt[i]);
#pragma unroll
    for (int o = 16; o; o >>= 1) sum += __shfl_xor_sync(0xffffffffu, sum, o);
    if ((tid & 31) == 0) red[tid >> 5] = sum;
    __syncthreads();
    if (tid < 32) {
        float s2 = (tid < 16) ? red[tid] : 0.f;
#pragma unroll
        for (int o = 8; o; o >>= 1) s2 += __shfl_xor_sync(0xffffffffu, s2, o);
        if (tid == 0) {
            float mean = s2 * (1.0f / 36864.0f);
            float inv_sw = fmaxf(mean, 1e-8f);
            s_w_sh = 1.0f / inv_sw;
            g_inv_sw = inv_sw;
        }
    }
    __syncthreads();
    float s_w = s_w_sh;

    for (int i = tid; i < 36864; i += 512) {
        float t = rintf(s_w * Wt[i]);
        t = fminf(fmaxf(t, -1.f), 1.f);
        int co  = i / 576;
        int rem = i - co * 576;
        int ci  = rem / 9;
        int tap = rem - ci * 9;
        g_w8[(tap * 64 + co) * 64 + ci] = (char)(int)t;
    }
}

// ---------------------------------------------------------------------------
// load one image row r (258 halo'd px x 64B s8) + inv_s into ring slot r&3.
// ---------------------------------------------------------------------------
__device__ __forceinline__ void load_row(uint32_t sb, int b, int r, int en, int tid) {
    if (!en) return;
    unsigned rok = ((unsigned)r < 256u) ? 1u : 0u;
    int rc = rok ? r : 0;
    size_t gbase = ((size_t)b << 16) | ((size_t)rc << 8);
    uint32_t slotb = sb + ACT_OFF + (uint32_t)(r & 3) * SLOT_B;
    for (int i = tid; i < 1032; i += 512) {          // 258 px * 4 chunks
        int px = i >> 2, c = i & 3;
        int w  = px - 1;
        unsigned ok = rok & (((unsigned)w < 256u) ? 1u : 0u);
        size_t off = ((gbase | (size_t)(ok ? w : 0)) << 6) | ((size_t)c << 4);
        uint32_t dst = slotb + (px << 6) + ((c ^ ((px >> 1) & 3)) << 4);
        CP_ASYNC(dst, (const char*)g_a8 + off, ok ? 16u : 0u);
    }
    if (tid < 64) {                                   // inv_s row: 256 floats
        uint32_t dst = sb + INVS_OFF + (uint32_t)(r & 3) * INVS_SLOT + 16 + (tid << 4);
        const char* src = (const char*)g_invs + ((gbase << 2) + ((size_t)tid << 4));
        CP_ASYNC(dst, src, rok ? 16u : 0u);
    }
}

// ---------------------------------------------------------------------------
// Kernel 3: conv. 512 threads, 16 warps; warp w -> out row h+(w&1),
// px [(w>>1)*32, +32) x 64 co. Per-tap IMMA + magic-number fp32 fold.
// ---------------------------------------------------------------------------
__global__ void __launch_bounds__(512, 1) conv_kernel(const float* __restrict__ bias,
                                                      float* __restrict__ out) {
    extern __shared__ __align__(1024) unsigned char smem[];
    uint32_t sb = smem_u32(smem);
    int tid = threadIdx.x, wid = tid >> 5, lane = tid & 31;

    int s_ = blockIdx.x;                    // strip 0..18
    int b  = blockIdx.y;                    // image 0..7
    int p0 = (s_ < 14) ? 7 * s_ : 98 + 6 * (s_ - 14);
    int p1 = p0 + ((s_ < 14) ? 7 : 6);

    // ---- weights -> smem (proven swizzle), bias, invs pads ----
    for (int i = tid; i < 2304; i += 512) {
        int tap = i >> 8;
        int rr  = i & 255;
        int co  = rr >> 2;
        int c   = rr & 3;
        uint32_t dst = sb + WS_OFF + (tap << 12) + (co << 6)
                     + ((c ^ ((co >> 1) & 3)) << 4);
        CP_ASYNC(dst, g_w8 + ((size_t)i << 4), 16u);
    }
    if (tid < 64) ((float*)(smem + BIAS_OFF))[tid] = bias[tid];
    if (tid < 8) {
        int slot = tid & 3, hi2 = tid >> 2;
        STS128Z(sb + INVS_OFF + slot * INVS_SLOT + (hi2 ? 1040 : 0));
    }

    // ---- prologue ----
    int h0 = 2 * p0;
#pragma unroll
    for (int rr = 0; rr < 4; rr++) load_row(sb, b, h0 - 1 + rr, 1, tid);
    CP_COMMIT();

    float inv_sw = g_inv_sw;

    // ---- per-thread ldmatrix geometry (proven, s8/64B rows) ----
    int px0    = (wid >> 1) << 5;           // 32-px column block
    int ho_off = wid & 1;
    int l15 = lane & 15;
    int hi  = lane >> 4;
    int lb  = lane & 7;
    int b1  = (lane >> 3) & 1;
    uint32_t sB   = (uint32_t)((lb >> 1) & 3);
    uint32_t boff = (uint32_t)(lb << 6);
    uint32_t aoffs[3], sA[3];
#pragma unroll
    for (int kw = 0; kw < 3; kw++) {
        int pxk = px0 + kw + l15;
        aoffs[kw] = (uint32_t)(pxk << 6);
        sA[kw]    = (uint32_t)((pxk >> 1) & 3);
    }
    int qr = lane >> 2, qc = (lane & 3) << 1;

    float facc[2][8][4];

    auto do_tap = [&](uint32_t slotb, const float* isl, int kw, int tap) {
        uint32_t wb = sb + WS_OFF + (tap << 12);
        uint32_t ab = slotb + aoffs[kw];
        float sc[2][2];
#pragma unroll
        for (int mt = 0; mt < 2; mt++) {
            int fi = px0 + mt * 16 + qr + kw + 3;    // input px + 4 (slot pad)
            sc[mt][0] = isl[fi];
            sc[mt][1] = isl[fi + 8];
        }
        uint32_t A[2][2][4];                         // [kk][mt]
#pragma unroll
        for (int kk = 0; kk < 2; kk++)
#pragma unroll
            for (int mt = 0; mt < 2; mt++) {
                uint32_t ca = (uint32_t)((kk << 1) | hi) ^ sA[kw];
                ldsm_x4(A[kk][mt], ab + (uint32_t)(mt << 10) + (ca << 4));
            }
        uint32_t cb0 = (((uint32_t)b1) ^ sB) << 4;
        uint32_t cb1 = (((uint32_t)(2 | b1)) ^ sB) << 4;
#pragma unroll
        for (int n = 0; n < 8; n++) {
            uint32_t B0[2], B1[2];
            ldsm_x2(B0, wb + (n << 9) + boff + cb0);
            ldsm_x2(B1, wb + (n << 9) + boff + cb1);
#pragma unroll
            for (int mt = 0; mt < 2; mt++) {
                int st[4];
                imma_m(st, A[0][mt], B0);            // G + 0x4B400000
                imma(st, A[1][mt], B1);
                // exact float(G) via magic reinterpret, then fold scale
                facc[mt][n][0] += (__int_as_float(st[0]) - MAGIC_F) * sc[mt][0];
                facc[mt][n][1] += (__int_as_float(st[1]) - MAGIC_F) * sc[mt][0];
                facc[mt][n][2] += (__int_as_float(st[2]) - MAGIC_F) * sc[mt][1];
                facc[mt][n][3] += (__int_as_float(st[3]) - MAGIC_F) * sc[mt][1];
            }
        }
    };

    auto do_phase = [&](int h, int kh) {
        int in_row = h + ho_off - 1 + kh;
        uint32_t slotb = sb + ACT_OFF + (uint32_t)(in_row & 3) * SLOT_B;
        const float* isl = (const float*)(smem + INVS_OFF + (in_row & 3) * INVS_SLOT);
#pragma unroll
        for (int kw = 0; kw < 3; kw++) do_tap(slotb, isl, kw, kh * 3 + kw);
    };

    for (int p = p0; p < p1; p++) {
        int h  = 2 * p;
        int en = (p + 1 < p1);

        CP_WAIT0();
        __syncthreads();

#pragma unroll
        for (int mt = 0; mt < 2; mt++)
#pragma unroll
            for (int n = 0; n < 8; n++)
#pragma unroll
                for (int e = 0; e < 4; e++) facc[mt][n][e] = 0.f;

        do_phase(h, 0);
        __syncthreads();                      // row h-1 dead
        load_row(sb, b, h + 3, en, tid);
        CP_COMMIT();

        do_phase(h, 1);
        __syncthreads();                      // row h dead
        load_row(sb, b, h + 4, en, tid);
        CP_COMMIT();

        do_phase(h, 2);

        // ---- epilogue: weight-scale + bias, fp32 NCHW ----
        const float* bs = (const float*)(smem + BIAS_OFF);
        int ho = h + ho_off;
        float* ob = out + ((size_t)b << 22) + ((size_t)ho << 8);
#pragma unroll
        for (int mt = 0; mt < 2; mt++) {
            int px = px0 + mt * 16 + qr;
#pragma unroll
            for (int n = 0; n < 8; n++) {
                int co = (n << 3) + qc;
                float bc0 = bs[co], bc1 = bs[co + 1];
                float* o0 = ob + ((size_t)co << 16) + px;
                float* o1 = ob + ((size_t)(co + 1) << 16) + px;
                o0[0] = facc[mt][n][0] * inv_sw + bc0;
                o1[0] = facc[mt][n][1] * inv_sw + bc1;
                o0[8] = facc[mt][n][2] * inv_sw + bc0;
                o1[8] = facc[mt][n][3] * inv_sw + bc1;
            }
        }
    }
    CP_WAIT0();
}

// ---------------------------------------------------------------------------
extern "C" void kernel_launch(void* const* d_in, const int* in_sizes, int n_in,
                              void* d_out, int out_size) {
    (void)in_sizes; (void)n_in; (void)out_size;
    const float* x    = (const float*)d_in[0];
    const float* Wt   = (const float*)d_in[1];
    const float* bias = (const float*)d_in[2];
    float* out = (float*)d_out;

    cudaFuncSetAttribute(conv_kernel, cudaFuncAttributeMaxDynamicSharedMemorySize,
                         SMEM_BYTES);

    norm_quant_kernel<<<8 * 65536 / 128, 128>>>(x);
    wq_kernel<<<1, 512>>>(Wt);
    dim3 grid(19, 8);
    conv_kernel<<<grid, 512, SMEM_BYTES>>>(bias, out);
}

// round 13
// speedup vs baseline: 1.6691x; 1.6691x over previous
#include <cuda_runtime.h>
#include <cuda_fp16.h>
#include <cstdint>
#include <math.h>

// ===========================================================================
// MMFConv2d sm_103a (base-target-safe), Round 13: FUSED norm+conv.
//   K2 (proven): ternary weight quant -> exact fp16 [tap][co][ci]
//   K3: per output half-row: cp.async raw fp32 row -> in-kernel LN+quant
//       (stream stats) -> fp16 ring slot -> 9-tap HMMA (R7/R11-proven
//       geometry, 8 warps x 16px x 64co) -> scale+bias epilogue.
//   Grid (19 row-strips x 16 image-halves) = 304 CTAs, 2 waves.
//   R4/R5 crash root-caused: image stride is b<<24 (was b<<26).
// ===========================================================================

__device__ __half g_w[9 * 64 * 64];              // fp16 ternary weights
__device__ float g_inv_sw;

// ---------------------------------------------------------------------------
__device__ __forceinline__ uint32_t smem_u32(const void* p) {
    uint32_t a;
    asm("{ .reg .u64 t; cvta.to.shared.u64 t, %1; cvt.u32.u64 %0, t; }"
        : "=r"(a) : "l"(p));
    return a;
}
__device__ __forceinline__ void ldsm_x4(uint32_t (&r)[4], uint32_t a) {
    asm volatile("ldmatrix.sync.aligned.m8n8.x4.shared.b16 {%0,%1,%2,%3}, [%4];"
                 : "=r"(r[0]), "=r"(r[1]), "=r"(r[2]), "=r"(r[3]) : "r"(a));
}
__device__ __forceinline__ void ldsm_x2(uint32_t (&r)[2], uint32_t a) {
    asm volatile("ldmatrix.sync.aligned.m8n8.x2.shared.b16 {%0,%1}, [%2];"
                 : "=r"(r[0]), "=r"(r[1]) : "r"(a));
}
__device__ __forceinline__ void mma16816(float (&d)[4], const uint32_t (&a)[4],
                                         const uint32_t (&b)[2]) {
    asm volatile(
        "mma.sync.aligned.m16n8k16.row.col.f32.f16.f16.f32 "
        "{%0,%1,%2,%3}, {%4,%5,%6,%7}, {%8,%9}, {%0,%1,%2,%3};"
        : "+f"(d[0]), "+f"(d[1]), "+f"(d[2]), "+f"(d[3])
        : "r"(a[0]), "r"(a[1]), "r"(a[2]), "r"(a[3]), "r"(b[0]), "r"(b[1]));
}
#define CP_ASYNC(dst, src, n) \
    asm volatile("cp.async.cg.shared.global [%0], [%1], 16, %2;" \
                 :: "r"(dst), "l"(src), "r"(n) : "memory")
#define CP_COMMIT() asm volatile("cp.async.commit_group;" ::: "memory")
#define CP_WAIT0()  asm volatile("cp.async.wait_group 0;" ::: "memory")
#define STS128(a, v) \
    asm volatile("st.shared.v4.b32 [%0], {%1,%2,%3,%4};" \
                 :: "r"(a), "r"((v).x), "r"((v).y), "r"((v).z), "r"((v).w) : "memory")

// ---------------------------------------------------------------------------
// smem layout
//   WS:   9 x 8192 fp16 weight tiles (swizzled)        = 73728
//   ACT:  4 ring slots x 130 px x 128 B fp16 (swizzled)= 66560
//   RAW:  64 ch x 136 px fp32 staged input row         = 34816
//   BIAS: 64 fp32                                      = 256
// ---------------------------------------------------------------------------
#define WS_OFF     0
#define ACT_OFF    73728
#define SLOT_B     16640                     // 130 * 128
#define RAW_OFF    (ACT_OFF + 4 * SLOT_B)    // 140288
#define RAW_CH_B   544                       // 136 px * 4 B
#define BIAS_OFF   (RAW_OFF + 64 * RAW_CH_B) // 175104
#define SMEM_BYTES (BIAS_OFF + 256)          // 175360

// ---------------------------------------------------------------------------
// Kernel 2 (proven): ternary weight quant -> exact fp16 [tap][co][ci]
// ---------------------------------------------------------------------------
__global__ void __launch_bounds__(512) wq_kernel(const float* __restrict__ Wt) {
    __shared__ float red[16];
    __shared__ float s_w_sh;
    int tid = threadIdx.x;

    float sum = 0.f;
    for (int i = tid; i < 36864; i += 512) sum += fabsf(Wt[i]);
#pragma unroll
    for (int o = 16; o; o >>= 1) sum += __shfl_xor_sync(0xffffffffu, sum, o);
    if ((tid & 31) == 0) red[tid >> 5] = sum;
    __syncthreads();
    if (tid < 32) {
        float s2 = (tid < 16) ? red[tid] : 0.f;
#pragma unroll
        for (int o = 8; o; o >>= 1) s2 += __shfl_xor_sync(0xffffffffu, s2, o);
        if (tid == 0) {
            float mean = s2 * (1.0f / 36864.0f);
            float inv_sw = fmaxf(mean, 1e-8f);
            s_w_sh = 1.0f / inv_sw;
            g_inv_sw = inv_sw;
        }
    }
    __syncthreads();
    float s_w = s_w_sh;

    for (int i = tid; i < 36864; i += 512) {
        float t = rintf(s_w * Wt[i]);
        t = fminf(fmaxf(t, -1.f), 1.f);
        int co  = i / 576;
        int rem = i - co * 576;
        int ci  = rem / 9;
        int tap = rem - ci * 9;
        g_w[(tap * 64 + co) * 64 + ci] = __float2half_rn(t);   // exact
    }
}

// ---------------------------------------------------------------------------
// stage raw fp32 row `row`, px [w0-4, w0+132) into RAW (zfill OOB).
// x byte offset: b<<24 | c<<18 | row<<10 | w<<2   (all verified)
// ---------------------------------------------------------------------------
__device__ __forceinline__ void raw_load(uint32_t sb, const float* __restrict__ x,
                                         int b, int row, int w0, int tid) {
    unsigned rok = ((unsigned)row < 256u) ? 1u : 0u;
    size_t base = ((size_t)b << 24) | ((size_t)(rok ? row : 0) << 10);
    for (int i = tid; i < 2176; i += 256) {        // 64 ch * 34 granules
        int c  = i / 34;
        int g  = i - c * 34;
        int ws = w0 - 4 + (g << 2);
        unsigned ok = rok & (((unsigned)ws < 256u) ? 1u : 0u);
        const char* src = (const char*)x + base + ((size_t)c << 18)
                        + ((size_t)(ok ? ws : 0) << 2);
        uint32_t dst = sb + RAW_OFF + c * RAW_CH_B + (g << 4);
        CP_ASYNC(dst, src, ok ? 16u : 0u);
    }
}

// ---------------------------------------------------------------------------
// normalize+quantize RAW -> fp16 ring slot (row&3). tid<130 active,
// thread t handles slot px t (abs w = w0-1+t, RAW col t+3).
// Stream stats: var = E[v^2]-mu^2, max|v-mu| = max(vmax-mu, mu-vmin).
// ---------------------------------------------------------------------------
__device__ __forceinline__ void norm_row(uint32_t sb, unsigned char* smem,
                                         int row, int tid) {
    if (tid >= 130) return;
    const float* raw = (const float*)(smem + RAW_OFF) + (tid + 3);
    float sum = 0.f, sumsq = 0.f, vmin = 1e30f, vmax = -1e30f;
#pragma unroll
    for (int c = 0; c < 64; c++) {
        float v = raw[c * 136];
        sum += v;
        sumsq = fmaf(v, v, sumsq);
        vmin = fminf(vmin, v);
        vmax = fmaxf(vmax, v);
    }
    float mu  = sum * (1.0f / 64.0f);
    float var = fmaxf(sumsq * (1.0f / 64.0f) - mu * mu, 0.f);
    float r   = rsqrtf(var + 1e-8f);
    float maxn  = fmaxf(fmaxf(vmax - mu, mu - vmin) * r, 1e-8f);
    float s     = 127.0f / maxn;
    float inv_s = maxn * (1.0f / 127.0f);

    uint32_t slotrow = sb + ACT_OFF + (uint32_t)(row & 3) * SLOT_B + (tid << 7);
    uint32_t sw = (uint32_t)(tid & 7) << 4;
#pragma unroll
    for (int cc = 0; cc < 8; cc++) {
        uint4 u;
        __half2 h2;
        float q0, q1;
        int c = cc << 3;
#define QV(k) fminf(fmaxf(rintf(s * (r * (raw[(c + (k)) * 136] - mu))), -128.f), 127.f) * inv_s
        q0 = QV(0); q1 = QV(1); h2 = __floats2half2_rn(q0, q1); u.x = *(uint32_t*)&h2;
        q0 = QV(2); q1 = QV(3); h2 = __floats2half2_rn(q0, q1); u.y = *(uint32_t*)&h2;
        q0 = QV(4); q1 = QV(5); h2 = __floats2half2_rn(q0, q1); u.z = *(uint32_t*)&h2;
        q0 = QV(6); q1 = QV(7); h2 = __floats2half2_rn(q0, q1); u.w = *(uint32_t*)&h2;
#undef QV
        STS128(slotrow + (((uint32_t)cc << 4) ^ sw), u);
    }
}

// ---------------------------------------------------------------------------
// Fused kernel. 256 threads, 8 warps; warp w -> px [w*16, +16) x 64 co of the
// current output half-row. Strip of rows, 4-slot fp16 ring, in-kernel norm.
// ---------------------------------------------------------------------------
__global__ void __launch_bounds__(256, 1) conv_kernel(const float* __restrict__ x,
                                                      const float* __restrict__ bias,
                                                      float* __restrict__ out) {
    extern __shared__ __align__(1024) unsigned char smem[];
    uint32_t sb = smem_u32(smem);
    int tid = threadIdx.x, wid = tid >> 5, lane = tid & 31;

    int s_ = blockIdx.x;                    // row strip 0..18
    int gy = blockIdx.y;                    // image-half 0..15
    int b    = gy >> 1;
    int w0   = (gy & 1) << 7;
    int r0 = (s_ < 9) ? 14 * s_ : 13 * s_ + 9;
    int r1 = r0 + ((s_ < 9) ? 14 : 13);

    // ---- weights -> smem (proven swizzle), bias ----
    for (int i = tid; i < 4608; i += 256) {
        int tap = i >> 9;
        int r   = i & 511;
        int co  = r >> 3;
        int c   = r & 7;
        uint32_t dst = sb + WS_OFF + (tap << 13) + (co << 7) + ((c ^ (co & 7)) << 4);
        CP_ASYNC(dst, (const char*)g_w + ((size_t)i << 4), 16u);
    }
    if (tid < 64) ((float*)(smem + BIAS_OFF))[tid] = bias[tid];
    CP_COMMIT();

    // ---- prologue: norm rows r0-1, r0, r0+1; raw(r0+2) in flight ----
#pragma unroll 1
    for (int rr = 0; rr < 3; rr++) {
        raw_load(sb, x, b, r0 - 1 + rr, w0, tid);
        CP_COMMIT(); CP_WAIT0(); __syncthreads();
        norm_row(sb, smem, r0 - 1 + rr, tid);
        __syncthreads();
    }
    raw_load(sb, x, b, r0 + 2, w0, tid);
    CP_COMMIT();

    float inv_sw = g_inv_sw;

    // ---- per-thread ldmatrix geometry (R7/R11-proven, fp16/128B rows) ----
    int px0  = wid << 4;                    // 16-px block within half-row
    int rA   = lane & 15;
    int colA = lane & 16;
    int rB   = lane & 7;
    int colB = ((lane >> 3) & 1) << 4;
    uint32_t rowBterm = (uint32_t)(rB << 7);
    uint32_t cxB = (uint32_t)(colB ^ (rB << 4));
    uint32_t rowbaseA[3], cxA[3];
#pragma unroll
    for (int kw = 0; kw < 3; kw++) {
        int loc = px0 + kw + rA;            // slot row (0..129)
        rowbaseA[kw] = (uint32_t)(loc << 7);
        cxA[kw]      = (uint32_t)(colA ^ ((loc & 7) << 4));
    }
    int qr = lane >> 2, qc = (lane & 3) << 1;

    for (int h = r0; h < r1; h++) {
        CP_WAIT0();
        __syncthreads();                     // raw(h+2) staged
        norm_row(sb, smem, h + 2, tid);      // slot (h+2)&3; frees RAW
        __syncthreads();
        raw_load(sb, x, b, h + 3, w0, tid);  // prefetch next raw
        CP_COMMIT();

        // ---- 9-tap HMMA on slots h-1, h, h+1 ----
        float acc[8][4];
#pragma unroll
        for (int n = 0; n < 8; n++)
#pragma unroll
            for (int e = 0; e < 4; e++) acc[n][e] = 0.f;

#pragma unroll
        for (int kh = 0; kh < 3; kh++) {
            uint32_t slotb = sb + ACT_OFF + (uint32_t)((h - 1 + kh) & 3) * SLOT_B;
#pragma unroll
            for (int kw = 0; kw < 3; kw++) {
                int tap = kh * 3 + kw;
                uint32_t wbase = sb + WS_OFF + (tap << 13) + rowBterm;
                uint32_t abuf  = slotb + rowbaseA[kw];
                uint32_t cxa   = cxA[kw];
#pragma unroll
                for (int kk = 0; kk < 4; kk++) {
                    uint32_t a[4];
                    ldsm_x4(a, abuf + (((uint32_t)kk << 5) ^ cxa));
                    uint32_t kB = ((uint32_t)kk << 5) ^ cxB;
#pragma unroll
                    for (int n = 0; n < 8; n++) {
                        uint32_t bf[2];
                        ldsm_x2(bf, wbase + ((uint32_t)n << 10) + kB);
                        mma16816(acc[n], a, bf);
                    }
                }
            }
        }

        // ---- epilogue: weight-scale + bias, fp32 NCHW ----
        const float* bs = (const float*)(smem + BIAS_OFF);
        int px = w0 + px0 + qr;
        float* ob = out + ((size_t)b << 22) + ((size_t)h << 8) + px;
#pragma unroll
        for (int n = 0; n < 8; n++) {
            int co = (n << 3) + qc;
            float bc0 = bs[co], bc1 = bs[co + 1];
            float* o0 = ob + ((size_t)co << 16);
            float* o1 = ob + ((size_t)(co + 1) << 16);
            o0[0] = acc[n][0] * inv_sw + bc0;
            o1[0] = acc[n][1] * inv_sw + bc1;
            o0[8] = acc[n][2] * inv_sw + bc0;
            o1[8] = acc[n][3] * inv_sw + bc1;
        }
    }
    CP_WAIT0();
}

// ---------------------------------------------------------------------------
extern "C" void kernel_launch(void* const* d_in, const int* in_sizes, int n_in,
                              void* d_out, int out_size) {
    (void)in_sizes; (void)n_in; (void)out_size;
    const float* x    = (const float*)d_in[0];
    const float* Wt   = (const float*)d_in[1];
    const float* bias = (const float*)d_in[2];
    float* out = (float*)d_out;

    cudaFuncSetAttribute(conv_kernel, cudaFuncAttributeMaxDynamicSharedMemorySize,
                         SMEM_BYTES);

    wq_kernel<<<1, 512>>>(Wt);
    dim3 grid(19, 16);
    conv_kernel<<<grid, 256, SMEM_BYTES>>>(x, bias, out);
}

// round 14
// speedup vs baseline: 1.6999x; 1.0185x over previous
#include <cuda_runtime.h>
#include <cuda_fp16.h>
#include <cstdint>
#include <math.h>

// ===========================================================================
// MMFConv2d sm_103a (base-target-safe), Round 14: fused norm+conv, pipelined.
//   Per row: raw prefetch (double-buffered, wait_group 1) -> MMA ISSUE (9
//   taps) -> norm(h+2) issued into the tensor-pipe drain -> epilogue.
//   One sync pair per row instead of R13's serialized norm-before-MMA.
// ===========================================================================

__device__ __half g_w[9 * 64 * 64];              // fp16 ternary weights
__device__ float g_inv_sw;

// ---------------------------------------------------------------------------
__device__ __forceinline__ uint32_t smem_u32(const void* p) {
    uint32_t a;
    asm("{ .reg .u64 t; cvta.to.shared.u64 t, %1; cvt.u32.u64 %0, t; }"
        : "=r"(a) : "l"(p));
    return a;
}
__device__ __forceinline__ void ldsm_x4(uint32_t (&r)[4], uint32_t a) {
    asm volatile("ldmatrix.sync.aligned.m8n8.x4.shared.b16 {%0,%1,%2,%3}, [%4];"
                 : "=r"(r[0]), "=r"(r[1]), "=r"(r[2]), "=r"(r[3]) : "r"(a));
}
__device__ __forceinline__ void ldsm_x2(uint32_t (&r)[2], uint32_t a) {
    asm volatile("ldmatrix.sync.aligned.m8n8.x2.shared.b16 {%0,%1}, [%2];"
                 : "=r"(r[0]), "=r"(r[1]) : "r"(a));
}
__device__ __forceinline__ void mma16816(float (&d)[4], const uint32_t (&a)[4],
                                         const uint32_t (&b)[2]) {
    asm volatile(
        "mma.sync.aligned.m16n8k16.row.col.f32.f16.f16.f32 "
        "{%0,%1,%2,%3}, {%4,%5,%6,%7}, {%8,%9}, {%0,%1,%2,%3};"
        : "+f"(d[0]), "+f"(d[1]), "+f"(d[2]), "+f"(d[3])
        : "r"(a[0]), "r"(a[1]), "r"(a[2]), "r"(a[3]), "r"(b[0]), "r"(b[1]));
}
#define CP_ASYNC(dst, src, n) \
    asm volatile("cp.async.cg.shared.global [%0], [%1], 16, %2;" \
                 :: "r"(dst), "l"(src), "r"(n) : "memory")
#define CP_COMMIT() asm volatile("cp.async.commit_group;" ::: "memory")
#define CP_WAIT0()  asm volatile("cp.async.wait_group 0;" ::: "memory")
#define CP_WAIT1()  asm volatile("cp.async.wait_group 1;" ::: "memory")
#define STS128(a, v) \
    asm volatile("st.shared.v4.b32 [%0], {%1,%2,%3,%4};" \
                 :: "r"(a), "r"((v).x), "r"((v).y), "r"((v).z), "r"((v).w) : "memory")

// ---------------------------------------------------------------------------
// smem layout
// ---------------------------------------------------------------------------
#define WS_OFF     0                         // 9 * 8192 = 73728
#define ACT_OFF    73728                     // 4 slots * 16640 = 66560
#define SLOT_B     16640                     // 130 px * 128 B
#define RAW_OFF    (ACT_OFF + 4 * SLOT_B)    // 140288; 2 bufs * 34816
#define RAW_BUF_B  34816                     // 64 ch * 136 px * 4 B
#define RAW_CH_B   544
#define BIAS_OFF   (RAW_OFF + 2 * RAW_BUF_B) // 209920
#define SMEM_BYTES (BIAS_OFF + 256)          // 210176

// ---------------------------------------------------------------------------
// Kernel 2 (proven): ternary weight quant -> exact fp16 [tap][co][ci]
// ---------------------------------------------------------------------------
__global__ void __launch_bounds__(512) wq_kernel(const float* __restrict__ Wt) {
    __shared__ float red[16];
    __shared__ float s_w_sh;
    int tid = threadIdx.x;

    float sum = 0.f;
    for (int i = tid; i < 36864; i += 512) sum += fabsf(Wt[i]);
#pragma unroll
    for (int o = 16; o; o >>= 1) sum += __shfl_xor_sync(0xffffffffu, sum, o);
    if ((tid & 31) == 0) red[tid >> 5] = sum;
    __syncthreads();
    if (tid < 32) {
        float s2 = (tid < 16) ? red[tid] : 0.f;
#pragma unroll
        for (int o = 8; o; o >>= 1) s2 += __shfl_xor_sync(0xffffffffu, s2, o);
        if (tid == 0) {
            float mean = s2 * (1.0f / 36864.0f);
            float inv_sw = fmaxf(mean, 1e-8f);
            s_w_sh = 1.0f / inv_sw;
            g_inv_sw = inv_sw;
        }
    }
    __syncthreads();
    float s_w = s_w_sh;

    for (int i = tid; i < 36864; i += 512) {
        float t = rintf(s_w * Wt[i]);
        t = fminf(fmaxf(t, -1.f), 1.f);
        int co  = i / 576;
        int rem = i - co * 576;
        int ci  = rem / 9;
        int tap = rem - ci * 9;
        g_w[(tap * 64 + co) * 64 + ci] = __float2half_rn(t);   // exact
    }
}

// ---------------------------------------------------------------------------
// stage raw fp32 row `row`, px [w0-4, w0+132) into RAW buf (row&1), zfill OOB.
// x byte offset: b<<24 | c<<18 | row<<10 | w<<2
// ---------------------------------------------------------------------------
__device__ __forceinline__ void raw_load(uint32_t sb, const float* __restrict__ x,
                                         int b, int row, int w0, int tid) {
    unsigned rok = ((unsigned)row < 256u) ? 1u : 0u;
    size_t base = ((size_t)b << 24) | ((size_t)(rok ? row : 0) << 10);
    uint32_t rb = sb + RAW_OFF + (uint32_t)(row & 1) * RAW_BUF_B;
    for (int i = tid; i < 2176; i += 256) {        // 64 ch * 34 granules
        int c  = i / 34;
        int g  = i - c * 34;
        int ws = w0 - 4 + (g << 2);
        unsigned ok = rok & (((unsigned)ws < 256u) ? 1u : 0u);
        const char* src = (const char*)x + base + ((size_t)c << 18)
                        + ((size_t)(ok ? ws : 0) << 2);
        uint32_t dst = rb + c * RAW_CH_B + (g << 4);
        CP_ASYNC(dst, src, ok ? 16u : 0u);
    }
}

// ---------------------------------------------------------------------------
// normalize+quantize RAW buf (row&1) -> fp16 ring slot (row&3). tid<130.
// ---------------------------------------------------------------------------
__device__ __forceinline__ void norm_row(uint32_t sb, unsigned char* smem,
                                         int row, int tid) {
    if (tid >= 130) return;
    const float* raw = (const float*)(smem + RAW_OFF + (row & 1) * RAW_BUF_B)
                     + (tid + 3);
    float sum = 0.f, sumsq = 0.f, vmin = 1e30f, vmax = -1e30f;
#pragma unroll
    for (int c = 0; c < 64; c++) {
        float v = raw[c * 136];
        sum += v;
        sumsq = fmaf(v, v, sumsq);
        vmin = fminf(vmin, v);
        vmax = fmaxf(vmax, v);
    }
    float mu  = sum * (1.0f / 64.0f);
    float var = fmaxf(sumsq * (1.0f / 64.0f) - mu * mu, 0.f);
    float r   = rsqrtf(var + 1e-8f);
    float maxn  = fmaxf(fmaxf(vmax - mu, mu - vmin) * r, 1e-8f);
    float s     = 127.0f / maxn;
    float inv_s = maxn * (1.0f / 127.0f);

    uint32_t slotrow = sb + ACT_OFF + (uint32_t)(row & 3) * SLOT_B + (tid << 7);
    uint32_t sw = (uint32_t)(tid & 7) << 4;
#pragma unroll
    for (int cc = 0; cc < 8; cc++) {
        uint4 u;
        __half2 h2;
        float q0, q1;
        int c = cc << 3;
#define QV(k) fminf(fmaxf(rintf(s * (r * (raw[(c + (k)) * 136] - mu))), -128.f), 127.f) * inv_s
        q0 = QV(0); q1 = QV(1); h2 = __floats2half2_rn(q0, q1); u.x = *(uint32_t*)&h2;
        q0 = QV(2); q1 = QV(3); h2 = __floats2half2_rn(q0, q1); u.y = *(uint32_t*)&h2;
        q0 = QV(4); q1 = QV(5); h2 = __floats2half2_rn(q0, q1); u.z = *(uint32_t*)&h2;
        q0 = QV(6); q1 = QV(7); h2 = __floats2half2_rn(q0, q1); u.w = *(uint32_t*)&h2;
#undef QV
        STS128(slotrow + (((uint32_t)cc << 4) ^ sw), u);
    }
}

// ---------------------------------------------------------------------------
// Fused kernel. 256 threads, 8 warps; warp w -> px [w*16, +16) x 64 co of the
// current output half-row. MMA issue first; norm rides the tensor drain.
// ---------------------------------------------------------------------------
__global__ void __launch_bounds__(256, 1) conv_kernel(const float* __restrict__ x,
                                                      const float* __restrict__ bias,
                                                      float* __restrict__ out) {
    extern __shared__ __align__(1024) unsigned char smem[];
    uint32_t sb = smem_u32(smem);
    int tid = threadIdx.x, wid = tid >> 5, lane = tid & 31;

    int s_ = blockIdx.x;                    // row strip 0..18
    int gy = blockIdx.y;                    // image-half 0..15
    int b    = gy >> 1;
    int w0   = (gy & 1) << 7;
    int r0 = (s_ < 9) ? 14 * s_ : 13 * s_ + 9;
    int r1 = r0 + ((s_ < 9) ? 14 : 13);

    // ---- weights -> smem (proven swizzle), bias ----
    for (int i = tid; i < 4608; i += 256) {
        int tap = i >> 9;
        int r   = i & 511;
        int co  = r >> 3;
        int c   = r & 7;
        uint32_t dst = sb + WS_OFF + (tap << 13) + (co << 7) + ((c ^ (co & 7)) << 4);
        CP_ASYNC(dst, (const char*)g_w + ((size_t)i << 4), 16u);
    }
    if (tid < 64) ((float*)(smem + BIAS_OFF))[tid] = bias[tid];
    CP_COMMIT();

    // ---- prologue: norm rows r0-1, r0, r0+1; raw(r0+2) left in flight ----
#pragma unroll 1
    for (int rr = 0; rr < 3; rr++) {
        raw_load(sb, x, b, r0 - 1 + rr, w0, tid);
        CP_COMMIT(); CP_WAIT0(); __syncthreads();
        norm_row(sb, smem, r0 - 1 + rr, tid);
        __syncthreads();
    }
    raw_load(sb, x, b, r0 + 2, w0, tid);
    CP_COMMIT();

    float inv_sw = g_inv_sw;

    // ---- per-thread ldmatrix geometry (proven) ----
    int px0  = wid << 4;                    // 16-px block within half-row
    int rA   = lane & 15;
    int colA = lane & 16;
    int rB   = lane & 7;
    int colB = ((lane >> 3) & 1) << 4;
    uint32_t rowBterm = (uint32_t)(rB << 7);
    uint32_t cxB = (uint32_t)(colB ^ (rB << 4));
    uint32_t rowbaseA[3], cxA[3];
#pragma unroll
    for (int kw = 0; kw < 3; kw++) {
        int loc = px0 + kw + rA;            // slot row (0..129)
        rowbaseA[kw] = (uint32_t)(loc << 7);
        cxA[kw]      = (uint32_t)(colA ^ ((loc & 7) << 4));
    }
    int qr = lane >> 2, qc = (lane & 3) << 1;

    for (int h = r0; h < r1; h++) {
        __syncthreads();                     // prev norm STS visible; slots stable

        raw_load(sb, x, b, h + 3, w0, tid);  // buf (h+3)&1 is free
        CP_COMMIT();

        // ---- 9-tap HMMA ISSUE on slots h-1, h, h+1 ----
        float acc[8][4];
#pragma unroll
        for (int n = 0; n < 8; n++)
#pragma unroll
            for (int e = 0; e < 4; e++) acc[n][e] = 0.f;

#pragma unroll
        for (int kh = 0; kh < 3; kh++) {
            uint32_t slotb = sb + ACT_OFF + (uint32_t)((h - 1 + kh) & 3) * SLOT_B;
#pragma unroll
            for (int kw = 0; kw < 3; kw++) {
                int tap = kh * 3 + kw;
                uint32_t wbase = sb + WS_OFF + (tap << 13) + rowBterm;
                uint32_t abuf  = slotb + rowbaseA[kw];
                uint32_t cxa   = cxA[kw];
#pragma unroll
                for (int kk = 0; kk < 4; kk++) {
                    uint32_t a[4];
                    ldsm_x4(a, abuf + (((uint32_t)kk << 5) ^ cxa));
                    uint32_t kB = ((uint32_t)kk << 5) ^ cxB;
#pragma unroll
                    for (int n = 0; n < 8; n++) {
                        uint32_t bf[2];
                        ldsm_x2(bf, wbase + ((uint32_t)n << 10) + kB);
                        mma16816(acc[n], a, bf);
                    }
                }
            }
        }

        // ---- raw(h+2) ready; norm rides the tensor-pipe drain ----
        CP_WAIT1();                          // group(h+2) done, (h+3) in flight
        __syncthreads();                     // cross-thread RAW visibility
        norm_row(sb, smem, h + 2, tid);      // writes slot (h+2)&3 (free)

        // ---- epilogue: weight-scale + bias, fp32 NCHW ----
        const float* bs = (const float*)(smem + BIAS_OFF);
        int px = w0 + px0 + qr;
        float* ob = out + ((size_t)b << 22) + ((size_t)h << 8) + px;
#pragma unroll
        for (int n = 0; n < 8; n++) {
            int co = (n << 3) + qc;
            float bc0 = bs[co], bc1 = bs[co + 1];
            float* o0 = ob + ((size_t)co << 16);
            float* o1 = ob + ((size_t)(co + 1) << 16);
            o0[0] = acc[n][0] * inv_sw + bc0;
            o1[0] = acc[n][1] * inv_sw + bc1;
            o0[8] = acc[n][2] * inv_sw + bc0;
            o1[8] = acc[n][3] * inv_sw + bc1;
        }
    }
    CP_WAIT0();
}

// ---------------------------------------------------------------------------
extern "C" void kernel_launch(void* const* d_in, const int* in_sizes, int n_in,
                              void* d_out, int out_size) {
    (void)in_sizes; (void)n_in; (void)out_size;
    const float* x    = (const float*)d_in[0];
    const float* Wt   = (const float*)d_in[1];
    const float* bias = (const float*)d_in[2];
    float* out = (float*)d_out;

    cudaFuncSetAttribute(conv_kernel, cudaFuncAttributeMaxDynamicSharedMemorySize,
                         SMEM_BYTES);

    wq_kernel<<<1, 512>>>(Wt);
    dim3 grid(19, 16);
    conv_kernel<<<grid, 256, SMEM_BYTES>>>(x, bias, out);
}

// round 15
// speedup vs baseline: 2.0344x; 1.1968x over previous
#include <cuda_runtime.h>
#include <cuda_fp16.h>
#include <cstdint>
#include <math.h>

// ===========================================================================
// MMFConv2d sm_103a (base-target-safe), Round 15:
//   R8 (best conv) with grid reshaped 19x8 (152 CTAs, 2-wave straggler) ->
//   16x8 (128 CTAs, ONE even wave; 8 row-pairs per CTA). Nothing else changed.
// ===========================================================================

__device__ __half g_a[(size_t)8 * 65536 * 64];   // fp16 NHWC activations
__device__ __half g_w[9 * 64 * 64];              // fp16 ternary weights
__device__ float g_inv_sw;

// ---------------------------------------------------------------------------
__device__ __forceinline__ uint32_t smem_u32(const void* p) {
    uint32_t a;
    asm("{ .reg .u64 t; cvta.to.shared.u64 t, %1; cvt.u32.u64 %0, t; }"
        : "=r"(a) : "l"(p));
    return a;
}
__device__ __forceinline__ void ldsm_x4(uint32_t (&r)[4], uint32_t a) {
    asm volatile("ldmatrix.sync.aligned.m8n8.x4.shared.b16 {%0,%1,%2,%3}, [%4];"
                 : "=r"(r[0]), "=r"(r[1]), "=r"(r[2]), "=r"(r[3]) : "r"(a));
}
__device__ __forceinline__ void ldsm_x2(uint32_t (&r)[2], uint32_t a) {
    asm volatile("ldmatrix.sync.aligned.m8n8.x2.shared.b16 {%0,%1}, [%2];"
                 : "=r"(r[0]), "=r"(r[1]) : "r"(a));
}
__device__ __forceinline__ void mma16816(float (&d)[4], const uint32_t (&a)[4],
                                         const uint32_t (&b)[2]) {
    asm volatile(
        "mma.sync.aligned.m16n8k16.row.col.f32.f16.f16.f32 "
        "{%0,%1,%2,%3}, {%4,%5,%6,%7}, {%8,%9}, {%0,%1,%2,%3};"
        : "+f"(d[0]), "+f"(d[1]), "+f"(d[2]), "+f"(d[3])
        : "r"(a[0]), "r"(a[1]), "r"(a[2]), "r"(a[3]), "r"(b[0]), "r"(b[1]));
}
#define CP_ASYNC(dst, src, n) \
    asm volatile("cp.async.cg.shared.global [%0], [%1], 16, %2;" \
                 :: "r"(dst), "l"(src), "r"(n) : "memory")
#define CP_COMMIT() asm volatile("cp.async.commit_group;" ::: "memory")
#define CP_WAIT0()  asm volatile("cp.async.wait_group 0;" ::: "memory")

// ---------------------------------------------------------------------------
// smem layout
// ---------------------------------------------------------------------------
#define WS_OFF     0                        // 9 * 8192 = 73728
#define ACT_OFF    73728                    // 4 row slots * 33024
#define SLOT_B     33024                    // 258 px * 128 B
#define BIAS_OFF   (ACT_OFF + 4 * SLOT_B)   // 205824
#define SMEM_BYTES (BIAS_OFF + 256)         // 206080

// ---------------------------------------------------------------------------
// Kernel 1 (proven): per-pixel LN + int8 fake-quant -> fp16 NHWC
// ---------------------------------------------------------------------------
__global__ void __launch_bounds__(128) norm_quant_kernel(const float* __restrict__ x) {
    int p  = blockIdx.x * 128 + threadIdx.x;
    int b  = p >> 16;
    int sp = p & 65535;

    const float* xb = x + (size_t)b * 64 * 65536 + sp;

    float v[64];
    float sum = 0.f;
#pragma unroll
    for (int c = 0; c < 64; c++) { v[c] = xb[(size_t)c << 16]; sum += v[c]; }
    float mu = sum * (1.0f / 64.0f);

    float var = 0.f, mx = 0.f;
#pragma unroll
    for (int c = 0; c < 64; c++) {
        float d = v[c] - mu;
        var += d * d;
        mx = fmaxf(mx, fabsf(d));
    }
    var *= (1.0f / 64.0f);
    float r = rsqrtf(var + 1e-8f);

    float maxn  = fmaxf(mx * r, 1e-8f);
    float s     = 127.0f / maxn;
    float inv_s = maxn * (1.0f / 127.0f);

    __half* yb = g_a + ((size_t)p << 6);
#pragma unroll
    for (int c = 0; c < 64; c += 8) {
        uint4 u;
        __half2 h2;
        float q0, q1;
#define QV(cc) fminf(fmaxf(rintf(s * (r * (v[cc] - mu))), -128.f), 127.f) * inv_s
        q0 = QV(c + 0); q1 = QV(c + 1); h2 = __floats2half2_rn(q0, q1); u.x = *(uint32_t*)&h2;
        q0 = QV(c + 2); q1 = QV(c + 3); h2 = __floats2half2_rn(q0, q1); u.y = *(uint32_t*)&h2;
        q0 = QV(c + 4); q1 = QV(c + 5); h2 = __floats2half2_rn(q0, q1); u.z = *(uint32_t*)&h2;
        q0 = QV(c + 6); q1 = QV(c + 7); h2 = __floats2half2_rn(q0, q1); u.w = *(uint32_t*)&h2;
#undef QV
        *(uint4*)(yb + c) = u;
    }
}

// ---------------------------------------------------------------------------
// Kernel 2 (proven): ternary weight quant -> exact fp16 [tap][co][ci]
// ---------------------------------------------------------------------------
__global__ void __launch_bounds__(512) wq_kernel(const float* __restrict__ Wt) {
    __shared__ float red[16];
    __shared__ float s_w_sh;
    int tid = threadIdx.x;

    float sum = 0.f;
    for (int i = tid; i < 36864; i += 512) sum += fabsf(Wt[i]);
#pragma unroll
    for (int o = 16; o; o >>= 1) sum += __shfl_xor_sync(0xffffffffu, sum, o);
    if ((tid & 31) == 0) red[tid >> 5] = sum;
    __syncthreads();
    if (tid < 32) {
        float s2 = (tid < 16) ? red[tid] : 0.f;
#pragma unroll
        for (int o = 8; o; o >>= 1) s2 += __shfl_xor_sync(0xffffffffu, s2, o);
        if (tid == 0) {
            float mean = s2 * (1.0f / 36864.0f);
            float inv_sw = fmaxf(mean, 1e-8f);
            s_w_sh = 1.0f / inv_sw;
            g_inv_sw = inv_sw;
        }
    }
    __syncthreads();
    float s_w = s_w_sh;

    for (int i = tid; i < 36864; i += 512) {
        float t = rintf(s_w * Wt[i]);
        t = fminf(fmaxf(t, -1.f), 1.f);
        int co  = i / 576;
        int rem = i - co * 576;
        int ci  = rem / 9;
        int tap = rem - ci * 9;
        g_w[(tap * 64 + co) * 64 + ci] = __float2half_rn(t);   // exact
    }
}

// ---------------------------------------------------------------------------
// load one image row r (258 halo'd px x 128B fp16) into ring slot r&3.
// ---------------------------------------------------------------------------
__device__ __forceinline__ void load_row(uint32_t sb, int b, int r, int en, int tid) {
    if (!en) return;
    unsigned rok = ((unsigned)r < 256u) ? 1u : 0u;
    int rc = rok ? r : 0;
    size_t gbase = ((size_t)b << 16) | ((size_t)rc << 8);
    uint32_t slotb = sb + ACT_OFF + (uint32_t)(r & 3) * SLOT_B;
    for (int i = tid; i < 2064; i += 256) {         // 258 px * 8 chunks
        int loc = i >> 3, c = i & 7;
        int w   = loc - 1;
        unsigned ok = rok & (((unsigned)w < 256u) ? 1u : 0u);
        size_t off = ((gbase | (size_t)(ok ? w : 0)) << 7) | ((size_t)c << 4);
        uint32_t dst = slotb + (loc << 7) + ((c ^ (loc & 7)) << 4);
        CP_ASYNC(dst, (const char*)g_a + off, ok ? 16u : 0u);
    }
}

// ---------------------------------------------------------------------------
// Kernel 3: conv. 256 threads, 8 warps; warp w -> out row h+(w&1),
// px [(w>>1)*64, +64) x all 64 co. Strip of 8 row-pairs, 4-slot row ring.
// ---------------------------------------------------------------------------
__global__ void __launch_bounds__(256, 1) conv_kernel(const float* __restrict__ bias,
                                                      float* __restrict__ out) {
    extern __shared__ __align__(1024) unsigned char smem[];
    uint32_t sb = smem_u32(smem);
    int tid = threadIdx.x, wid = tid >> 5, lane = tid & 31;

    int s_ = blockIdx.x;                    // strip 0..15
    int b  = blockIdx.y;                    // image 0..7
    int p0 = s_ << 3;                       // 8 row-pairs per strip (even)
    int p1 = p0 + 8;

    // ---- weights -> smem (proven swizzle), bias ----
    for (int i = tid; i < 4608; i += 256) {
        int tap = i >> 9;
        int r   = i & 511;
        int co  = r >> 3;
        int c   = r & 7;
        uint32_t dst = sb + WS_OFF + (tap << 13) + (co << 7) + ((c ^ (co & 7)) << 4);
        CP_ASYNC(dst, (const char*)g_w + ((size_t)i << 4), 16u);
    }
    if (tid < 64) ((float*)(smem + BIAS_OFF))[tid] = bias[tid];

    // ---- prologue: rows 2*p0-1 .. 2*p0+2 into the 4 ring slots ----
    int h0 = 2 * p0;
#pragma unroll
    for (int rr = 0; rr < 4; rr++) load_row(sb, b, h0 - 1 + rr, 1, tid);
    CP_COMMIT();

    float inv_sw = g_inv_sw;

    // ---- per-thread ldmatrix geometry (proven) ----
    int px0    = (wid >> 1) << 6;
    int ho_off = wid & 1;
    int rA   = lane & 15;
    int colA = lane & 16;
    int rB   = lane & 7;
    int colB = ((lane >> 3) & 1) << 4;
    uint32_t rowBterm = (uint32_t)(rB << 7);
    uint32_t cxB = (uint32_t)(colB ^ (rB << 4));
    uint32_t rowbaseA[3], cxA[3];
#pragma unroll
    for (int kw = 0; kw < 3; kw++) {
        rowbaseA[kw] = (uint32_t)((px0 + kw + rA) << 7);
        cxA[kw]      = (uint32_t)(colA ^ (((kw + rA) & 7) << 4));
    }
    int qr = lane >> 2, qc = (lane & 3) << 1;

    float acc[4][8][4];

    auto do_phase = [&](int h, int kh) {
        int in_row = h + ho_off - 1 + kh;
        uint32_t slotb = sb + ACT_OFF + (uint32_t)(in_row & 3) * SLOT_B;
#pragma unroll
        for (int kw = 0; kw < 3; kw++) {
            int tap = kh * 3 + kw;
            uint32_t wb  = sb + WS_OFF + (tap << 13) + rowBterm;
            uint32_t ab  = slotb + rowbaseA[kw];
            uint32_t cxa = cxA[kw];
#pragma unroll
            for (int kk = 0; kk < 4; kk++) {
                uint32_t a[4][4];
#pragma unroll
                for (int mt = 0; mt < 4; mt++)
                    ldsm_x4(a[mt], ab + mt * 2048 + (((uint32_t)kk << 5) ^ cxa));
                uint32_t kB = ((uint32_t)kk << 5) ^ cxB;
#pragma unroll
                for (int n = 0; n < 8; n++) {
                    uint32_t bf[2];
                    ldsm_x2(bf, wb + ((uint32_t)n << 10) + kB);
#pragma unroll
                    for (int mt = 0; mt < 4; mt++)
                        mma16816(acc[mt][n], a[mt], bf);
                }
            }
        }
    };

    for (int p = p0; p < p1; p++) {
        int h  = 2 * p;
        int en = (p + 1 < p1);

        CP_WAIT0();
        __syncthreads();                       // all prefetched rows visible

#pragma unroll
        for (int mt = 0; mt < 4; mt++)
#pragma unroll
            for (int n = 0; n < 8; n++)
#pragma unroll
                for (int e = 0; e < 4; e++) acc[mt][n][e] = 0.f;

        do_phase(h, 0);                        // reads rows h-1 (out h), h (out h+1)
        __syncthreads();                       // row h-1 now dead
        load_row(sb, b, h + 3, en, tid);
        CP_COMMIT();

        do_phase(h, 1);                        // reads rows h, h+1
        __syncthreads();                       // row h now dead
        load_row(sb, b, h + 4, en, tid);
        CP_COMMIT();

        do_phase(h, 2);                        // reads rows h+1, h+2

        // ---- epilogue: weight-scale + bias, fp32 NCHW ----
        const float* bs = (const float*)(smem + BIAS_OFF);
        int ho = h + ho_off;
        float* ob = out + ((size_t)b << 22) + ((size_t)ho << 8);
#pragma unroll
        for (int mt = 0; mt < 4; mt++) {
            int px = px0 + mt * 16 + qr;
#pragma unroll
            for (int n = 0; n < 8; n++) {
                int co = (n << 3) + qc;
                float bc0 = bs[co], bc1 = bs[co + 1];
                float* o0 = ob + ((size_t)co << 16) + px;
                float* o1 = ob + ((size_t)(co + 1) << 16) + px;
                o0[0] = acc[mt][n][0] * inv_sw + bc0;
                o1[0] = acc[mt][n][1] * inv_sw + bc1;
                o0[8] = acc[mt][n][2] * inv_sw + bc0;
                o1[8] = acc[mt][n][3] * inv_sw + bc1;
            }
        }
    }
    CP_WAIT0();
}

// ---------------------------------------------------------------------------
extern "C" void kernel_launch(void* const* d_in, const int* in_sizes, int n_in,
                              void* d_out, int out_size) {
    (void)in_sizes; (void)n_in; (void)out_size;
    const float* x    = (const float*)d_in[0];
    const float* Wt   = (const float*)d_in[1];
    const float* bias = (const float*)d_in[2];
    float* out = (float*)d_out;

    cudaFuncSetAttribute(conv_kernel, cudaFuncAttributeMaxDynamicSharedMemorySize,
                         SMEM_BYTES);

    norm_quant_kernel<<<8 * 65536 / 128, 128>>>(x);
    wq_kernel<<<1, 512>>>(Wt);
    dim3 grid(16, 8);
    conv_kernel<<<grid, 256, SMEM_BYTES>>>(bias, out);
}

// round 16
// speedup vs baseline: 2.1124x; 1.0383x over previous
#include <cuda_runtime.h>
#include <cuda_fp16.h>
#include <cstdint>
#include <math.h>

// ===========================================================================
// MMFConv2d sm_103a (base-target-safe), Round 16:
//   K1 (new): merged norm+wq launch. Norm = 2 threads/pixel (32 ch each,
//   shfl-combined streaming stats) -> ~2x occupancy. Block 8192 does wq.
//   K2: conv = R8 byte-for-byte (best measured: 19x8 strips, 256 thr).
// ===========================================================================

__device__ __half g_a[(size_t)8 * 65536 * 64];   // fp16 NHWC activations
__device__ __half g_w[9 * 64 * 64];              // fp16 ternary weights
__device__ float g_inv_sw;

// ---------------------------------------------------------------------------
__device__ __forceinline__ uint32_t smem_u32(const void* p) {
    uint32_t a;
    asm("{ .reg .u64 t; cvta.to.shared.u64 t, %1; cvt.u32.u64 %0, t; }"
        : "=r"(a) : "l"(p));
    return a;
}
__device__ __forceinline__ void ldsm_x4(uint32_t (&r)[4], uint32_t a) {
    asm volatile("ldmatrix.sync.aligned.m8n8.x4.shared.b16 {%0,%1,%2,%3}, [%4];"
                 : "=r"(r[0]), "=r"(r[1]), "=r"(r[2]), "=r"(r[3]) : "r"(a));
}
__device__ __forceinline__ void ldsm_x2(uint32_t (&r)[2], uint32_t a) {
    asm volatile("ldmatrix.sync.aligned.m8n8.x2.shared.b16 {%0,%1}, [%2];"
                 : "=r"(r[0]), "=r"(r[1]) : "r"(a));
}
__device__ __forceinline__ void mma16816(float (&d)[4], const uint32_t (&a)[4],
                                         const uint32_t (&b)[2]) {
    asm volatile(
        "mma.sync.aligned.m16n8k16.row.col.f32.f16.f16.f32 "
        "{%0,%1,%2,%3}, {%4,%5,%6,%7}, {%8,%9}, {%0,%1,%2,%3};"
        : "+f"(d[0]), "+f"(d[1]), "+f"(d[2]), "+f"(d[3])
        : "r"(a[0]), "r"(a[1]), "r"(a[2]), "r"(a[3]), "r"(b[0]), "r"(b[1]));
}
#define CP_ASYNC(dst, src, n) \
    asm volatile("cp.async.cg.shared.global [%0], [%1], 16, %2;" \
                 :: "r"(dst), "l"(src), "r"(n) : "memory")
#define CP_COMMIT() asm volatile("cp.async.commit_group;" ::: "memory")
#define CP_WAIT0()  asm volatile("cp.async.wait_group 0;" ::: "memory")

// ---------------------------------------------------------------------------
// smem layout (conv)
// ---------------------------------------------------------------------------
#define WS_OFF     0                        // 9 * 8192 = 73728
#define ACT_OFF    73728                    // 4 row slots * 33024
#define SLOT_B     33024                    // 258 px * 128 B
#define BIAS_OFF   (ACT_OFF + 4 * SLOT_B)   // 205824
#define SMEM_BYTES (BIAS_OFF + 256)         // 206080

// ---------------------------------------------------------------------------
// Kernel 1: merged norm (blocks 0..8191) + weight quant (block 8192).
// Norm: 128 thr = 64 px, 2 thr/px x 32 ch, shfl-combined streaming stats.
// ---------------------------------------------------------------------------
__global__ void __launch_bounds__(128) norm_wq_kernel(const float* __restrict__ x,
                                                      const float* __restrict__ Wt) {
    int tid = threadIdx.x;

    if (blockIdx.x == 8192) {
        // ---- weight quant (proven math, 128-thread variant) ----
        __shared__ float red[4];
        __shared__ float s_w_sh;
        float sum = 0.f;
        for (int i = tid; i < 36864; i += 128) sum += fabsf(Wt[i]);
#pragma unroll
        for (int o = 16; o; o >>= 1) sum += __shfl_xor_sync(0xffffffffu, sum, o);
        if ((tid & 31) == 0) red[tid >> 5] = sum;
        __syncthreads();
        if (tid == 0) {
            float s2 = red[0] + red[1] + red[2] + red[3];
            float mean = s2 * (1.0f / 36864.0f);
            float inv_sw = fmaxf(mean, 1e-8f);
            s_w_sh = 1.0f / inv_sw;
            g_inv_sw = inv_sw;
        }
        __syncthreads();
        float s_w = s_w_sh;
        for (int i = tid; i < 36864; i += 128) {
            float t = rintf(s_w * Wt[i]);
            t = fminf(fmaxf(t, -1.f), 1.f);
            int co  = i / 576;
            int rem = i - co * 576;
            int ci  = rem / 9;
            int tap = rem - ci * 9;
            g_w[(tap * 64 + co) * 64 + ci] = __float2half_rn(t);   // exact
        }
        return;
    }

    // ---- per-pixel LN + int8 fake-quant -> fp16 NHWC ----
    int p    = blockIdx.x * 64 + (tid >> 1);
    int half = tid & 1;
    int b  = p >> 16;
    int sp = p & 65535;

    const float* xb = x + ((size_t)b << 22) + (size_t)sp
                    + ((size_t)(half << 5) << 16);

    float v[32];
    float sum = 0.f, sumsq = 0.f, vmin = 1e30f, vmax = -1e30f;
#pragma unroll
    for (int c = 0; c < 32; c++) {
        float t = xb[(size_t)c << 16];
        v[c] = t;
        sum += t;
        sumsq = fmaf(t, t, sumsq);
        vmin = fminf(vmin, t);
        vmax = fmaxf(vmax, t);
    }
    sum   += __shfl_xor_sync(0xffffffffu, sum, 1);
    sumsq += __shfl_xor_sync(0xffffffffu, sumsq, 1);
    vmin = fminf(vmin, __shfl_xor_sync(0xffffffffu, vmin, 1));
    vmax = fmaxf(vmax, __shfl_xor_sync(0xffffffffu, vmax, 1));

    float mu  = sum * (1.0f / 64.0f);
    float var = fmaxf(sumsq * (1.0f / 64.0f) - mu * mu, 0.f);
    float r   = rsqrtf(var + 1e-8f);
    float maxn  = fmaxf(fmaxf(vmax - mu, mu - vmin) * r, 1e-8f);
    float s     = 127.0f / maxn;
    float inv_s = maxn * (1.0f / 127.0f);

    __half* yb = g_a + ((size_t)p << 6) + (half << 5);
#pragma unroll
    for (int c = 0; c < 32; c += 8) {
        uint4 u;
        __half2 h2;
        float q0, q1;
#define QV(cc) fminf(fmaxf(rintf(s * (r * (v[cc] - mu))), -128.f), 127.f) * inv_s
        q0 = QV(c + 0); q1 = QV(c + 1); h2 = __floats2half2_rn(q0, q1); u.x = *(uint32_t*)&h2;
        q0 = QV(c + 2); q1 = QV(c + 3); h2 = __floats2half2_rn(q0, q1); u.y = *(uint32_t*)&h2;
        q0 = QV(c + 4); q1 = QV(c + 5); h2 = __floats2half2_rn(q0, q1); u.z = *(uint32_t*)&h2;
        q0 = QV(c + 6); q1 = QV(c + 7); h2 = __floats2half2_rn(q0, q1); u.w = *(uint32_t*)&h2;
#undef QV
        *(uint4*)(yb + c) = u;
    }
}

// ---------------------------------------------------------------------------
// load one image row r (258 halo'd px x 128B fp16) into ring slot r&3.
// ---------------------------------------------------------------------------
__device__ __forceinline__ void load_row(uint32_t sb, int b, int r, int en, int tid) {
    if (!en) return;
    unsigned rok = ((unsigned)r < 256u) ? 1u : 0u;
    int rc = rok ? r : 0;
    size_t gbase = ((size_t)b << 16) | ((size_t)rc << 8);
    uint32_t slotb = sb + ACT_OFF + (uint32_t)(r & 3) * SLOT_B;
    for (int i = tid; i < 2064; i += 256) {         // 258 px * 8 chunks
        int loc = i >> 3, c = i & 7;
        int w   = loc - 1;
        unsigned ok = rok & (((unsigned)w < 256u) ? 1u : 0u);
        size_t off = ((gbase | (size_t)(ok ? w : 0)) << 7) | ((size_t)c << 4);
        uint32_t dst = slotb + (loc << 7) + ((c ^ (loc & 7)) << 4);
        CP_ASYNC(dst, (const char*)g_a + off, ok ? 16u : 0u);
    }
}

// ---------------------------------------------------------------------------
// Kernel 2 (R8 byte-for-byte): conv. 256 threads, 8 warps; warp w -> out row
// h+(w&1), px [(w>>1)*64, +64) x all 64 co. 19x8 strips, 4-slot row ring.
// ---------------------------------------------------------------------------
__global__ void __launch_bounds__(256, 1) conv_kernel(const float* __restrict__ bias,
                                                      float* __restrict__ out) {
    extern __shared__ __align__(1024) unsigned char smem[];
    uint32_t sb = smem_u32(smem);
    int tid = threadIdx.x, wid = tid >> 5, lane = tid & 31;

    int s_ = blockIdx.x;                    // strip 0..18
    int b  = blockIdx.y;                    // image 0..7
    int p0 = (s_ < 14) ? 7 * s_ : 98 + 6 * (s_ - 14);
    int p1 = p0 + ((s_ < 14) ? 7 : 6);      // row-pair range

    // ---- weights -> smem (proven swizzle), bias ----
    for (int i = tid; i < 4608; i += 256) {
        int tap = i >> 9;
        int r   = i & 511;
        int co  = r >> 3;
        int c   = r & 7;
        uint32_t dst = sb + WS_OFF + (tap << 13) + (co << 7) + ((c ^ (co & 7)) << 4);
        CP_ASYNC(dst, (const char*)g_w + ((size_t)i << 4), 16u);
    }
    if (tid < 64) ((float*)(smem + BIAS_OFF))[tid] = bias[tid];

    // ---- prologue: rows 2*p0-1 .. 2*p0+2 into the 4 ring slots ----
    int h0 = 2 * p0;
#pragma unroll
    for (int rr = 0; rr < 4; rr++) load_row(sb, b, h0 - 1 + rr, 1, tid);
    CP_COMMIT();

    float inv_sw = g_inv_sw;

    // ---- per-thread ldmatrix geometry (proven) ----
    int px0    = (wid >> 1) << 6;
    int ho_off = wid & 1;
    int rA   = lane & 15;
    int colA = lane & 16;
    int rB   = lane & 7;
    int colB = ((lane >> 3) & 1) << 4;
    uint32_t rowBterm = (uint32_t)(rB << 7);
    uint32_t cxB = (uint32_t)(colB ^ (rB << 4));
    uint32_t rowbaseA[3], cxA[3];
#pragma unroll
    for (int kw = 0; kw < 3; kw++) {
        rowbaseA[kw] = (uint32_t)((px0 + kw + rA) << 7);
        cxA[kw]      = (uint32_t)(colA ^ (((kw + rA) & 7) << 4));
    }
    int qr = lane >> 2, qc = (lane & 3) << 1;

    float acc[4][8][4];

    auto do_phase = [&](int h, int kh) {
        int in_row = h + ho_off - 1 + kh;
        uint32_t slotb = sb + ACT_OFF + (uint32_t)(in_row & 3) * SLOT_B;
#pragma unroll
        for (int kw = 0; kw < 3; kw++) {
            int tap = kh * 3 + kw;
            uint32_t wb  = sb + WS_OFF + (tap << 13) + rowBterm;
            uint32_t ab  = slotb + rowbaseA[kw];
            uint32_t cxa = cxA[kw];
#pragma unroll
            for (int kk = 0; kk < 4; kk++) {
                uint32_t a[4][4];
#pragma unroll
                for (int mt = 0; mt < 4; mt++)
                    ldsm_x4(a[mt], ab + mt * 2048 + (((uint32_t)kk << 5) ^ cxa));
                uint32_t kB = ((uint32_t)kk << 5) ^ cxB;
#pragma unroll
                for (int n = 0; n < 8; n++) {
                    uint32_t bf[2];
                    ldsm_x2(bf, wb + ((uint32_t)n << 10) + kB);
#pragma unroll
                    for (int mt = 0; mt < 4; mt++)
                        mma16816(acc[mt][n], a[mt], bf);
                }
            }
        }
    };

    for (int p = p0; p < p1; p++) {
        int h  = 2 * p;
        int en = (p + 1 < p1);

        CP_WAIT0();
        __syncthreads();                       // all prefetched rows visible

#pragma unroll
        for (int mt = 0; mt < 4; mt++)
#pragma unroll
            for (int n = 0; n < 8; n++)
#pragma unroll
                for (int e = 0; e < 4; e++) acc[mt][n][e] = 0.f;

        do_phase(h, 0);                        // reads rows h-1 (out h), h (out h+1)
        __syncthreads();                       // row h-1 now dead
        load_row(sb, b, h + 3, en, tid);
        CP_COMMIT();

        do_phase(h, 1);                        // reads rows h, h+1
        __syncthreads();                       // row h now dead
        load_row(sb, b, h + 4, en, tid);
        CP_COMMIT();

        do_phase(h, 2);                        // reads rows h+1, h+2

        // ---- epilogue: weight-scale + bias, fp32 NCHW ----
        const float* bs = (const float*)(smem + BIAS_OFF);
        int ho = h + ho_off;
        float* ob = out + ((size_t)b << 22) + ((size_t)ho << 8);
#pragma unroll
        for (int mt = 0; mt < 4; mt++) {
            int px = px0 + mt * 16 + qr;
#pragma unroll
            for (int n = 0; n < 8; n++) {
                int co = (n << 3) + qc;
                float bc0 = bs[co], bc1 = bs[co + 1];
                float* o0 = ob + ((size_t)co << 16) + px;
                float* o1 = ob + ((size_t)(co + 1) << 16) + px;
                o0[0] = acc[mt][n][0] * inv_sw + bc0;
                o1[0] = acc[mt][n][1] * inv_sw + bc1;
                o0[8] = acc[mt][n][2] * inv_sw + bc0;
                o1[8] = acc[mt][n][3] * inv_sw + bc1;
            }
        }
    }
    CP_WAIT0();
}

// ---------------------------------------------------------------------------
extern "C" void kernel_launch(void* const* d_in, const int* in_sizes, int n_in,
                              void* d_out, int out_size) {
    (void)in_sizes; (void)n_in; (void)out_size;
    const float* x    = (const float*)d_in[0];
    const float* Wt   = (const float*)d_in[1];
    const float* bias = (const float*)d_in[2];
    float* out = (float*)d_out;

    cudaFuncSetAttribute(conv_kernel, cudaFuncAttributeMaxDynamicSharedMemorySize,
                         SMEM_BYTES);

    norm_wq_kernel<<<8193, 128>>>(x, Wt);
    dim3 grid(19, 8);
    conv_kernel<<<grid, 256, SMEM_BYTES>>>(bias, out);
}

// round 17
// speedup vs baseline: 2.1967x; 1.0399x over previous
#include <cuda_runtime.h>
#include <cuda_fp16.h>
#include <cstdint>
#include <math.h>

// ===========================================================================
// MMFConv2d sm_103a (base-target-safe), Round 17:
//   K1: wq (proven 512-thr launch, no tail).
//   K2: norm 2-thr/px, warp-uniform halves (half = tid>>6): R8-grade 128B
//       load coalescing + ~50 regs (2x occupancy); halves merge via smem.
//   K3: conv byte-identical to R16/R8 (98.5us measured, tensor 64.3%).
// ===========================================================================

__device__ __half g_a[(size_t)8 * 65536 * 64];   // fp16 NHWC activations
__device__ __half g_w[9 * 64 * 64];              // fp16 ternary weights
__device__ float g_inv_sw;

// ---------------------------------------------------------------------------
__device__ __forceinline__ uint32_t smem_u32(const void* p) {
    uint32_t a;
    asm("{ .reg .u64 t; cvta.to.shared.u64 t, %1; cvt.u32.u64 %0, t; }"
        : "=r"(a) : "l"(p));
    return a;
}
__device__ __forceinline__ void ldsm_x4(uint32_t (&r)[4], uint32_t a) {
    asm volatile("ldmatrix.sync.aligned.m8n8.x4.shared.b16 {%0,%1,%2,%3}, [%4];"
                 : "=r"(r[0]), "=r"(r[1]), "=r"(r[2]), "=r"(r[3]) : "r"(a));
}
__device__ __forceinline__ void ldsm_x2(uint32_t (&r)[2], uint32_t a) {
    asm volatile("ldmatrix.sync.aligned.m8n8.x2.shared.b16 {%0,%1}, [%2];"
                 : "=r"(r[0]), "=r"(r[1]) : "r"(a));
}
__device__ __forceinline__ void mma16816(float (&d)[4], const uint32_t (&a)[4],
                                         const uint32_t (&b)[2]) {
    asm volatile(
        "mma.sync.aligned.m16n8k16.row.col.f32.f16.f16.f32 "
        "{%0,%1,%2,%3}, {%4,%5,%6,%7}, {%8,%9}, {%0,%1,%2,%3};"
        : "+f"(d[0]), "+f"(d[1]), "+f"(d[2]), "+f"(d[3])
        : "r"(a[0]), "r"(a[1]), "r"(a[2]), "r"(a[3]), "r"(b[0]), "r"(b[1]));
}
#define CP_ASYNC(dst, src, n) \
    asm volatile("cp.async.cg.shared.global [%0], [%1], 16, %2;" \
                 :: "r"(dst), "l"(src), "r"(n) : "memory")
#define CP_COMMIT() asm volatile("cp.async.commit_group;" ::: "memory")
#define CP_WAIT0()  asm volatile("cp.async.wait_group 0;" ::: "memory")

// ---------------------------------------------------------------------------
// smem layout (conv)
// ---------------------------------------------------------------------------
#define WS_OFF     0                        // 9 * 8192 = 73728
#define ACT_OFF    73728                    // 4 row slots * 33024
#define SLOT_B     33024                    // 258 px * 128 B
#define BIAS_OFF   (ACT_OFF + 4 * SLOT_B)   // 205824
#define SMEM_BYTES (BIAS_OFF + 256)         // 206080

// ---------------------------------------------------------------------------
// Kernel 1 (proven): ternary weight quant -> exact fp16 [tap][co][ci]
// ---------------------------------------------------------------------------
__global__ void __launch_bounds__(512) wq_kernel(const float* __restrict__ Wt) {
    __shared__ float red[16];
    __shared__ float s_w_sh;
    int tid = threadIdx.x;

    float sum = 0.f;
    for (int i = tid; i < 36864; i += 512) sum += fabsf(Wt[i]);
#pragma unroll
    for (int o = 16; o; o >>= 1) sum += __shfl_xor_sync(0xffffffffu, sum, o);
    if ((tid & 31) == 0) red[tid >> 5] = sum;
    __syncthreads();
    if (tid < 32) {
        float s2 = (tid < 16) ? red[tid] : 0.f;
#pragma unroll
        for (int o = 8; o; o >>= 1) s2 += __shfl_xor_sync(0xffffffffu, s2, o);
        if (tid == 0) {
            float mean = s2 * (1.0f / 36864.0f);
            float inv_sw = fmaxf(mean, 1e-8f);
            s_w_sh = 1.0f / inv_sw;
            g_inv_sw = inv_sw;
        }
    }
    __syncthreads();
    float s_w = s_w_sh;

    for (int i = tid; i < 36864; i += 512) {
        float t = rintf(s_w * Wt[i]);
        t = fminf(fmaxf(t, -1.f), 1.f);
        int co  = i / 576;
        int rem = i - co * 576;
        int ci  = rem / 9;
        int tap = rem - ci * 9;
        g_w[(tap * 64 + co) * 64 + ci] = __float2half_rn(t);   // exact
    }
}

// ---------------------------------------------------------------------------
// Kernel 2: per-pixel LN + int8 fake-quant -> fp16 NHWC.
// 128 thr = 64 px; half = tid>>6 (warp-uniform), px = tid&63.
// Each warp loads 32 consecutive px of one 32-ch half: full 128B lines.
// ---------------------------------------------------------------------------
__global__ void __launch_bounds__(128) norm_quant_kernel(const float* __restrict__ x) {
    __shared__ float st[4][64];
    int tid = threadIdx.x;
    int h2  = tid >> 6;                      // channel half 0/1 (warp-uniform)
    int j   = tid & 63;                      // pixel within block

    int p  = blockIdx.x * 64 + j;
    int b  = p >> 16;
    int sp = p & 65535;

    const float* xb = x + ((size_t)b << 22) + (size_t)sp
                    + ((size_t)(h2 << 5) << 16);

    float v[32];
    float sum = 0.f, sumsq = 0.f, vmin = 1e30f, vmax = -1e30f;
#pragma unroll
    for (int c = 0; c < 32; c++) {
        float t = xb[(size_t)c << 16];
        v[c] = t;
        sum += t;
        sumsq = fmaf(t, t, sumsq);
        vmin = fminf(vmin, t);
        vmax = fmaxf(vmax, t);
    }

    if (h2) {
        st[0][j] = sum; st[1][j] = sumsq; st[2][j] = vmin; st[3][j] = vmax;
    }
    __syncthreads();
    if (!h2) {
        sum   += st[0][j];
        sumsq += st[1][j];
        vmin = fminf(vmin, st[2][j]);
        vmax = fmaxf(vmax, st[3][j]);
        float mu  = sum * (1.0f / 64.0f);
        float var = fmaxf(sumsq * (1.0f / 64.0f) - mu * mu, 0.f);
        float r   = rsqrtf(var + 1e-8f);
        float maxn  = fmaxf(fmaxf(vmax - mu, mu - vmin) * r, 1e-8f);
        st[0][j] = mu;
        st[1][j] = r;
        st[2][j] = 127.0f / maxn;
        st[3][j] = maxn * (1.0f / 127.0f);
    }
    __syncthreads();
    float mu    = st[0][j];
    float r     = st[1][j];
    float s     = st[2][j];
    float inv_s = st[3][j];

    __half* yb = g_a + ((size_t)p << 6) + (h2 << 5);
#pragma unroll
    for (int c = 0; c < 32; c += 8) {
        uint4 u;
        __half2 hh;
        float q0, q1;
#define QV(cc) fminf(fmaxf(rintf(s * (r * (v[cc] - mu))), -128.f), 127.f) * inv_s
        q0 = QV(c + 0); q1 = QV(c + 1); hh = __floats2half2_rn(q0, q1); u.x = *(uint32_t*)&hh;
        q0 = QV(c + 2); q1 = QV(c + 3); hh = __floats2half2_rn(q0, q1); u.y = *(uint32_t*)&hh;
        q0 = QV(c + 4); q1 = QV(c + 5); hh = __floats2half2_rn(q0, q1); u.z = *(uint32_t*)&hh;
        q0 = QV(c + 6); q1 = QV(c + 7); hh = __floats2half2_rn(q0, q1); u.w = *(uint32_t*)&hh;
#undef QV
        *(uint4*)(yb + c) = u;
    }
}

// ---------------------------------------------------------------------------
// load one image row r (258 halo'd px x 128B fp16) into ring slot r&3.
// ---------------------------------------------------------------------------
__device__ __forceinline__ void load_row(uint32_t sb, int b, int r, int en, int tid) {
    if (!en) return;
    unsigned rok = ((unsigned)r < 256u) ? 1u : 0u;
    int rc = rok ? r : 0;
    size_t gbase = ((size_t)b << 16) | ((size_t)rc << 8);
    uint32_t slotb = sb + ACT_OFF + (uint32_t)(r & 3) * SLOT_B;
    for (int i = tid; i < 2064; i += 256) {         // 258 px * 8 chunks
        int loc = i >> 3, c = i & 7;
        int w   = loc - 1;
        unsigned ok = rok & (((unsigned)w < 256u) ? 1u : 0u);
        size_t off = ((gbase | (size_t)(ok ? w : 0)) << 7) | ((size_t)c << 4);
        uint32_t dst = slotb + (loc << 7) + ((c ^ (loc & 7)) << 4);
        CP_ASYNC(dst, (const char*)g_a + off, ok ? 16u : 0u);
    }
}

// ---------------------------------------------------------------------------
// Kernel 3 (R8/R16 byte-identical): conv. 256 threads, 8 warps; warp w ->
// out row h+(w&1), px [(w>>1)*64, +64) x 64 co. 19x8 strips, 4-slot ring.
// ---------------------------------------------------------------------------
__global__ void __launch_bounds__(256, 1) conv_kernel(const float* __restrict__ bias,
                                                      float* __restrict__ out) {
    extern __shared__ __align__(1024) unsigned char smem[];
    uint32_t sb = smem_u32(smem);
    int tid = threadIdx.x, wid = tid >> 5, lane = tid & 31;

    int s_ = blockIdx.x;                    // strip 0..18
    int b  = blockIdx.y;                    // image 0..7
    int p0 = (s_ < 14) ? 7 * s_ : 98 + 6 * (s_ - 14);
    int p1 = p0 + ((s_ < 14) ? 7 : 6);      // row-pair range

    // ---- weights -> smem (proven swizzle), bias ----
    for (int i = tid; i < 4608; i += 256) {
        int tap = i >> 9;
        int r   = i & 511;
        int co  = r >> 3;
        int c   = r & 7;
        uint32_t dst = sb + WS_OFF + (tap << 13) + (co << 7) + ((c ^ (co & 7)) << 4);
        CP_ASYNC(dst, (const char*)g_w + ((size_t)i << 4), 16u);
    }
    if (tid < 64) ((float*)(smem + BIAS_OFF))[tid] = bias[tid];

    // ---- prologue: rows 2*p0-1 .. 2*p0+2 into the 4 ring slots ----
    int h0 = 2 * p0;
#pragma unroll
    for (int rr = 0; rr < 4; rr++) load_row(sb, b, h0 - 1 + rr, 1, tid);
    CP_COMMIT();

    float inv_sw = g_inv_sw;

    // ---- per-thread ldmatrix geometry (proven) ----
    int px0    = (wid >> 1) << 6;
    int ho_off = wid & 1;
    int rA   = lane & 15;
    int colA = lane & 16;
    int rB   = lane & 7;
    int colB = ((lane >> 3) & 1) << 4;
    uint32_t rowBterm = (uint32_t)(rB << 7);
    uint32_t cxB = (uint32_t)(colB ^ (rB << 4));
    uint32_t rowbaseA[3], cxA[3];
#pragma unroll
    for (int kw = 0; kw < 3; kw++) {
        rowbaseA[kw] = (uint32_t)((px0 + kw + rA) << 7);
        cxA[kw]      = (uint32_t)(colA ^ (((kw + rA) & 7) << 4));
    }
    int qr = lane >> 2, qc = (lane & 3) << 1;

    float acc[4][8][4];

    auto do_phase = [&](int h, int kh) {
        int in_row = h + ho_off - 1 + kh;
        uint32_t slotb = sb + ACT_OFF + (uint32_t)(in_row & 3) * SLOT_B;
#pragma unroll
        for (int kw = 0; kw < 3; kw++) {
            int tap = kh * 3 + kw;
            uint32_t wb  = sb + WS_OFF + (tap << 13) + rowBterm;
            uint32_t ab  = slotb + rowbaseA[kw];
            uint32_t cxa = cxA[kw];
#pragma unroll
            for (int kk = 0; kk < 4; kk++) {
                uint32_t a[4][4];
#pragma unroll
                for (int mt = 0; mt < 4; mt++)
                    ldsm_x4(a[mt], ab + mt * 2048 + (((uint32_t)kk << 5) ^ cxa));
                uint32_t kB = ((uint32_t)kk << 5) ^ cxB;
#pragma unroll
                for (int n = 0; n < 8; n++) {
                    uint32_t bf[2];
                    ldsm_x2(bf, wb + ((uint32_t)n << 10) + kB);
#pragma unroll
                    for (int mt = 0; mt < 4; mt++)
                        mma16816(acc[mt][n], a[mt], bf);
                }
            }
        }
    };

    for (int p = p0; p < p1; p++) {
        int h  = 2 * p;
        int en = (p + 1 < p1);

        CP_WAIT0();
        __syncthreads();                       // all prefetched rows visible

#pragma unroll
        for (int mt = 0; mt < 4; mt++)
#pragma unroll
            for (int n = 0; n < 8; n++)
#pragma unroll
                for (int e = 0; e < 4; e++) acc[mt][n][e] = 0.f;

        do_phase(h, 0);                        // reads rows h-1 (out h), h (out h+1)
        __syncthreads();                       // row h-1 now dead
        load_row(sb, b, h + 3, en, tid);
        CP_COMMIT();

        do_phase(h, 1);                        // reads rows h, h+1
        __syncthreads();                       // row h now dead
        load_row(sb, b, h + 4, en, tid);
        CP_COMMIT();

        do_phase(h, 2);                        // reads rows h+1, h+2

        // ---- epilogue: weight-scale + bias, fp32 NCHW ----
        const float* bs = (const float*)(smem + BIAS_OFF);
        int ho = h + ho_off;
        float* ob = out + ((size_t)b << 22) + ((size_t)ho << 8);
#pragma unroll
        for (int mt = 0; mt < 4; mt++) {
            int px = px0 + mt * 16 + qr;
#pragma unroll
            for (int n = 0; n < 8; n++) {
                int co = (n << 3) + qc;
                float bc0 = bs[co], bc1 = bs[co + 1];
                float* o0 = ob + ((size_t)co << 16) + px;
                float* o1 = ob + ((size_t)(co + 1) << 16) + px;
                o0[0] = acc[mt][n][0] * inv_sw + bc0;
                o1[0] = acc[mt][n][1] * inv_sw + bc1;
                o0[8] = acc[mt][n][2] * inv_sw + bc0;
                o1[8] = acc[mt][n][3] * inv_sw + bc1;
            }
        }
    }
    CP_WAIT0();
}

// ---------------------------------------------------------------------------
extern "C" void kernel_launch(void* const* d_in, const int* in_sizes, int n_in,
                              void* d_out, int out_size) {
    (void)in_sizes; (void)n_in; (void)out_size;
    const float* x    = (const float*)d_in[0];
    const float* Wt   = (const float*)d_in[1];
    const float* bias = (const float*)d_in[2];
    float* out = (float*)d_out;

    cudaFuncSetAttribute(conv_kernel, cudaFuncAttributeMaxDynamicSharedMemorySize,
                         SMEM_BYTES);

    wq_kernel<<<1, 512>>>(Wt);
    norm_quant_kernel<<<8192, 128>>>(x);
    dim3 grid(19, 8);
    conv_kernel<<<grid, 256, SMEM_BYTES>>>(bias, out);
}